// round 3
// baseline (speedup 1.0000x reference)
#include <cuda_runtime.h>
#include <math.h>

#define FEAT_I 512
#define H_DIM  1024
#define CODE   640
#define CODE_G 320
#define FEAT_G 256
#define B_     8
#define T_     4096
#define N_     (B_ * T_)          // 32768
#define Q_ELEMS ((size_t)B_ * 512 * T_)   // 16,777,216

typedef unsigned long long ull;

// Scratch (allocation-free rule: __device__ globals)
__device__ float g_h[(size_t)N_ * H_DIM];        // 128 MB
__device__ float g_logits[(size_t)N_ * CODE];    //  80 MB

__device__ __forceinline__ void fma2(ull& d, ull a, ull b, ull c) {
    asm("fma.rn.f32x2 %0, %1, %2, %3;" : "=l"(d) : "l"(a), "l"(b), "l"(c));
}
__device__ __forceinline__ void unpack2(float& lo, float& hi, ull v) {
    asm("mov.b64 {%0, %1}, %2;" : "=f"(lo), "=f"(hi) : "l"(v));
}

// ---------------------------------------------------------------------------
// GEMM1: h = relu(x @ W1 + b1),  x[m,k] = series[b, k, t]  (m = b*T + t)
// 128x128 tile, BK=8, 256 threads, 8x8 microtile via fma.rn.f32x2 (FFMA2).
// A is duplicated in shared (As2[k][2m]=As2[k][2m+1]) so (a,a) pairs load
// with a single LDS — no pack MOVs in the inner loop.
// ---------------------------------------------------------------------------
__global__ __launch_bounds__(256, 2)
void gemm1_kernel(const float* __restrict__ series,
                  const float* __restrict__ W1,
                  const float* __restrict__ b1)
{
    __shared__ __align__(16) float As2[8][256];   // k-major, m duplicated
    __shared__ __align__(16) float Bs[8][128];

    const int tid   = threadIdx.x;
    const int jBase = blockIdx.x * 128;
    const int mBase = blockIdx.y * 128;
    const int b     = mBase / T_;                // tile never crosses b (4096%128==0)
    const int t0    = mBase % T_;

    const float* Abase = series + (size_t)b * FEAT_I * T_ + t0;

    const int lk  = tid >> 5;          // 0..7
    const int lm4 = (tid & 31) * 4;    // 0..124
    const int tm  = tid >> 4;          // 0..15
    const int tn  = tid & 15;          // 0..15

    ull acc[8][4];
#pragma unroll
    for (int i = 0; i < 8; i++)
#pragma unroll
        for (int j = 0; j < 4; j++) acc[i][j] = 0ull;

    for (int k0 = 0; k0 < FEAT_I; k0 += 8) {
        float4 va = *(const float4*)&Abase[(size_t)(k0 + lk) * T_ + lm4];
        *(float4*)&As2[lk][2 * lm4]     = make_float4(va.x, va.x, va.y, va.y);
        *(float4*)&As2[lk][2 * lm4 + 4] = make_float4(va.z, va.z, va.w, va.w);
        *(float4*)&Bs[lk][lm4] = *(const float4*)&W1[(size_t)(k0 + lk) * H_DIM + jBase + lm4];
        __syncthreads();
#pragma unroll
        for (int k = 0; k < 8; k++) {
            ull a2[8], b2[4];
            const ull* ap = (const ull*)&As2[k][tm * 16];
            const ull* bp = (const ull*)&Bs[k][tn * 8];
#pragma unroll
            for (int i = 0; i < 8; i++) a2[i] = ap[i];
#pragma unroll
            for (int j = 0; j < 4; j++) b2[j] = bp[j];
#pragma unroll
            for (int i = 0; i < 8; i++)
#pragma unroll
                for (int j = 0; j < 4; j++)
                    fma2(acc[i][j], a2[i], b2[j], acc[i][j]);
        }
        __syncthreads();
    }

    // epilogue: +bias, relu, store
    float bias[8];
#pragma unroll
    for (int j = 0; j < 8; j++) bias[j] = b1[jBase + tn * 8 + j];
#pragma unroll
    for (int i = 0; i < 8; i++) {
        const int m = mBase + tm * 8 + i;
        float v[8];
#pragma unroll
        for (int j = 0; j < 4; j++) {
            float lo, hi;
            unpack2(lo, hi, acc[i][j]);
            float z0 = lo + bias[2 * j];
            float z1 = hi + bias[2 * j + 1];
            v[2 * j]     = z0 > 0.f ? z0 : 0.f;
            v[2 * j + 1] = z1 > 0.f ? z1 : 0.f;
        }
        float* hrow = g_h + (size_t)m * H_DIM + jBase + tn * 8;
        *(float4*)&hrow[0] = *(float4*)&v[0];
        *(float4*)&hrow[4] = *(float4*)&v[4];
    }
}

// ---------------------------------------------------------------------------
// GEMM2: z = h @ W2 + b2 + gumbel(u), stored as perturbed logits.
// Same FFMA2 scheme; A-tile transposed to k-major duplicated layout in shared.
// ---------------------------------------------------------------------------
__global__ __launch_bounds__(256, 2)
void gemm2_kernel(const float* __restrict__ W2,
                  const float* __restrict__ b2,
                  const float* __restrict__ gumbel_u)
{
    __shared__ __align__(16) float As2[8][256];   // k-major, m duplicated
    __shared__ __align__(16) float Bs[8][128];

    const int tid   = threadIdx.x;
    const int jBase = blockIdx.x * 128;     // grid.x = 5 -> 640 cols
    const int mBase = blockIdx.y * 128;

    const int lm  = tid >> 1;          // 0..127
    const int lp  = (tid & 1) * 4;     // 0 / 4
    const int lk  = tid >> 5;
    const int lj4 = (tid & 31) * 4;
    const int tm  = tid >> 4;
    const int tn  = tid & 15;

    ull acc[8][4];
#pragma unroll
    for (int i = 0; i < 8; i++)
#pragma unroll
        for (int j = 0; j < 4; j++) acc[i][j] = 0ull;

    for (int k0 = 0; k0 < H_DIM; k0 += 8) {
        float4 va = *(const float4*)&g_h[(size_t)(mBase + lm) * H_DIM + k0 + lp];
#pragma unroll
        for (int j = 0; j < 4; j++) {
            float val = (&va.x)[j];
            *(float2*)&As2[lp + j][2 * lm] = make_float2(val, val);
        }
        *(float4*)&Bs[lk][lj4] = *(const float4*)&W2[(size_t)(k0 + lk) * CODE + jBase + lj4];
        __syncthreads();
#pragma unroll
        for (int k = 0; k < 8; k++) {
            ull a2[8], b2v[4];
            const ull* ap = (const ull*)&As2[k][tm * 16];
            const ull* bp = (const ull*)&Bs[k][tn * 8];
#pragma unroll
            for (int i = 0; i < 8; i++) a2[i] = ap[i];
#pragma unroll
            for (int j = 0; j < 4; j++) b2v[j] = bp[j];
#pragma unroll
            for (int i = 0; i < 8; i++)
#pragma unroll
                for (int j = 0; j < 4; j++)
                    fma2(acc[i][j], a2[i], b2v[j], acc[i][j]);
        }
        __syncthreads();
    }

    // epilogue: + bias + gumbel noise, store perturbed logits
#pragma unroll
    for (int i = 0; i < 8; i++) {
        const int row = mBase + tm * 8 + i;
        const size_t base = (size_t)row * CODE + jBase + tn * 8;
        float v[8];
#pragma unroll
        for (int j = 0; j < 4; j++)
            unpack2(v[2 * j], v[2 * j + 1], acc[i][j]);
#pragma unroll
        for (int j = 0; j < 8; j++) {
            const int col = jBase + tn * 8 + j;
            float z = v[j] + b2[col];
            float u = gumbel_u[base + j];
            float g = -logf(-logf(u + 1e-10f) + 1e-10f);
            g_logits[base + j] = z + g;
        }
    }
}

// ---------------------------------------------------------------------------
// Kernel 3: per-(n, group) argmax over 320 perturbed logits (first-index
// tiebreak), then codebook gather with t-coalesced transposed writes.
// ---------------------------------------------------------------------------
__global__ __launch_bounds__(256)
void argmax_gather_kernel(const float* __restrict__ codebook,
                          float* __restrict__ out)
{
    const int t0 = blockIdx.x * 32;
    const int b  = blockIdx.y;
    const int g  = blockIdx.z;

    __shared__ int s_idx[32];

    const int tid  = threadIdx.x;
    const int lane = tid & 31;
    const int w    = tid >> 5;

#pragma unroll
    for (int rr = 0; rr < 4; rr++) {
        const int tl = w * 4 + rr;
        const int n  = b * T_ + t0 + tl;
        const float* lp = g_logits + (size_t)n * CODE + g * CODE_G;
        float best = -INFINITY;
        int   bi   = 0;
        for (int c = lane; c < CODE_G; c += 32) {
            float v = lp[c];
            if (v > best) { best = v; bi = c; }
        }
#pragma unroll
        for (int off = 16; off; off >>= 1) {
            float ov = __shfl_down_sync(0xffffffffu, best, off);
            int   oi = __shfl_down_sync(0xffffffffu, bi,   off);
            if (ov > best || (ov == best && oi < bi)) { best = ov; bi = oi; }
        }
        if (lane == 0) {
            s_idx[tl] = bi;
            out[Q_ELEMS + (size_t)n * 2 + g] = (float)bi;
        }
    }
    __syncthreads();

    const int tx  = tid & 31;
    const int fy  = tid >> 5;
    const int idx = s_idx[tx];
    const float* cbrow = codebook + ((size_t)g * CODE_G + idx) * FEAT_G;
    float* outb = out + ((size_t)b * 512 + g * FEAT_G) * T_ + t0;
    for (int f = fy; f < FEAT_G; f += 8)
        outb[(size_t)f * T_ + tx] = cbrow[f];
}

// ---------------------------------------------------------------------------
extern "C" void kernel_launch(void* const* d_in, const int* in_sizes, int n_in,
                              void* d_out, int out_size)
{
    const float* series   = (const float*)d_in[0];
    const float* gumbel_u = (const float*)d_in[1];
    const float* W1       = (const float*)d_in[2];
    const float* b1       = (const float*)d_in[3];
    const float* W2       = (const float*)d_in[4];
    const float* b2       = (const float*)d_in[5];
    const float* codebook = (const float*)d_in[6];
    float* out = (float*)d_out;

    gemm1_kernel<<<dim3(H_DIM / 128, N_ / 128), 256>>>(series, W1, b1);
    gemm2_kernel<<<dim3(CODE / 128, N_ / 128), 256>>>(W2, b2, gumbel_u);
    argmax_gather_kernel<<<dim3(T_ / 32, B_, 2), 256>>>(codebook, out);
}

// round 5
// speedup vs baseline: 1.6123x; 1.6123x over previous
#include <cuda_runtime.h>
#include <cuda_bf16.h>
#include <math.h>
#include <stdint.h>

#define FEAT_I 512
#define H_DIM  1024
#define CODE   640
#define CODE_G 320
#define FEAT_G 256
#define B_     8
#define T_     4096
#define N_     (B_ * T_)                  // 32768
#define Q_ELEMS ((size_t)B_ * 512 * T_)   // 16,777,216

#define K3_1 (3 * FEAT_I)    // 1536
#define K3_2 (3 * H_DIM)     // 3072

// ---------------------------------------------------------------------------
// Device scratch (allocation-free rule)
// ---------------------------------------------------------------------------
__device__ __nv_bfloat16 g_xb [(size_t)N_    * K3_1];  // x planes   [m][p*512+k]
__device__ __nv_bfloat16 g_w1b[(size_t)H_DIM * K3_1];  // W1^T planes[n][p*512+k]
__device__ __nv_bfloat16 g_hb [(size_t)N_    * K3_2];  // h planes   [m][p*1024+k]
__device__ __nv_bfloat16 g_w2b[(size_t)CODE  * K3_2];  // W2^T planes[n][p*1024+k]
__device__ float         g_logits[(size_t)N_ * CODE];  // perturbed logits

// 6 cross-terms of the 3-plane split
__constant__ int PA6[6] = {0, 1, 0, 2, 0, 1};
__constant__ int PB6[6] = {0, 0, 1, 0, 2, 1};

// ---------------------------------------------------------------------------
// PTX helpers (all arch-agnostic: sm_80-class instructions)
// ---------------------------------------------------------------------------
__device__ __forceinline__ uint32_t smem_u32(const void* p) {
    uint32_t a;
    asm("{ .reg .u64 t; cvta.to.shared.u64 t, %1; cvt.u32.u64 %0, t; }" : "=r"(a) : "l"(p));
    return a;
}
__device__ __forceinline__ void cp16(uint32_t saddr, const void* g) {
    asm volatile("cp.async.cg.shared.global [%0], [%1], 16;" :: "r"(saddr), "l"(g));
}
#define CP_COMMIT() asm volatile("cp.async.commit_group;" ::: "memory")
#define CP_WAIT0()  asm volatile("cp.async.wait_group 0;" ::: "memory")

__device__ __forceinline__ void ldsm4(uint32_t& a, uint32_t& b, uint32_t& c, uint32_t& d,
                                      uint32_t addr) {
    asm volatile("ldmatrix.sync.aligned.m8n8.x4.shared.b16 {%0,%1,%2,%3}, [%4];"
                 : "=r"(a), "=r"(b), "=r"(c), "=r"(d) : "r"(addr));
}
__device__ __forceinline__ void mma16816(float* d, const uint32_t* a, const uint32_t* b) {
    asm volatile("mma.sync.aligned.m16n8k16.row.col.f32.bf16.bf16.f32 "
                 "{%0,%1,%2,%3},{%4,%5,%6,%7},{%8,%9},{%0,%1,%2,%3};"
                 : "+f"(d[0]), "+f"(d[1]), "+f"(d[2]), "+f"(d[3])
                 : "r"(a[0]), "r"(a[1]), "r"(a[2]), "r"(a[3]), "r"(b[0]), "r"(b[1]));
}

__device__ __forceinline__ void split3(float v, __nv_bfloat16& a, __nv_bfloat16& b,
                                       __nv_bfloat16& c) {
    a = __float2bfloat16(v);
    float r = v - __bfloat162float(a);
    b = __float2bfloat16(r);
    float r2 = r - __bfloat162float(b);
    c = __float2bfloat16(r2);
}

// ---------------------------------------------------------------------------
// Core: 128x128 block, acc += sum over 6 plane-pairs of A(128xK) * B(128xK)^T.
// smem: A buf0 [0,16K) buf1 [16K,32K); B buf0 [32K,48K) buf1 [48K,64K).
// ---------------------------------------------------------------------------
template<int KPLANE, int NCH>
__device__ __forceinline__ void gemm_core(const char* __restrict__ Abase,
                                          const char* __restrict__ Bbase,
                                          int tid, uint32_t smb,
                                          float acc[4][4][4]) {
    const int lane = tid & 31, wid = tid >> 5;
    const int warp_m = wid >> 2;     // 0..1
    const int warp_n = wid & 3;      // 0..3
    const uint32_t sA = smb;
    const uint32_t sB = smb + 32768;
    const int r0 = tid >> 3, cc = tid & 7;
    const int KCH = KPLANE / 64;
    const size_t ROWB = (size_t)KPLANE * 6;   // 3 planes * 2 bytes

    auto issue = [&](int c, int buf) {
        const int pair = c / KCH, kc = c % KCH;
        const size_t ac = (size_t)(PA6[pair] * KPLANE + kc * 64) * 2;
        const size_t bc = (size_t)(PB6[pair] * KPLANE + kc * 64) * 2;
#pragma unroll
        for (int i = 0; i < 4; i++) {
            const int r = r0 + 32 * i;
            const uint32_t so = (uint32_t)(r * 128 + ((cc ^ (r & 7)) * 16));
            cp16(sA + buf * 16384 + so, Abase + (size_t)r * ROWB + ac + cc * 16);
            cp16(sB + buf * 16384 + so, Bbase + (size_t)r * ROWB + bc + cc * 16);
        }
    };

    issue(0, 0);
    CP_COMMIT();

    for (int c = 0; c < NCH; c++) {
        CP_WAIT0();
        __syncthreads();
        if (c + 1 < NCH) { issue(c + 1, (c + 1) & 1); CP_COMMIT(); }
        const uint32_t bA = sA + (c & 1) * 16384;
        const uint32_t bB = sB + (c & 1) * 16384;
#pragma unroll
        for (int kk = 0; kk < 4; kk++) {
            uint32_t afr[4][4], bfr[2][4];
            const int lrow = lane & 15;
            const int ch = kk * 2 + (lane >> 4);
#pragma unroll
            for (int im = 0; im < 4; im++) {
                const int r = warp_m * 64 + im * 16 + lrow;
                ldsm4(afr[im][0], afr[im][1], afr[im][2], afr[im][3],
                      bA + r * 128 + ((ch ^ (r & 7)) * 16));
            }
#pragma unroll
            for (int i2 = 0; i2 < 2; i2++) {
                const int r = warp_n * 32 + i2 * 16 + lrow;
                ldsm4(bfr[i2][0], bfr[i2][1], bfr[i2][2], bfr[i2][3],
                      bB + r * 128 + ((ch ^ (r & 7)) * 16));
            }
#pragma unroll
            for (int im = 0; im < 4; im++)
#pragma unroll
                for (int in = 0; in < 4; in++) {
                    uint32_t bb[2] = { bfr[in >> 1][in & 1], bfr[in >> 1][(in & 1) + 2] };
                    mma16816(acc[im][in], afr[im], bb);
                }
        }
    }
    __syncthreads();
}

// ---------------------------------------------------------------------------
// GEMM1: h = relu(x@W1 + b1) -> split3 -> g_hb (coalesced via smem staging)
// ---------------------------------------------------------------------------
__global__ __launch_bounds__(256, 2)
void gemm1_mma(const float* __restrict__ b1) {
    extern __shared__ char smem[];
    const uint32_t smb = smem_u32(smem);
    const int tid = threadIdx.x, lane = tid & 31, wid = tid >> 5;
    const int warp_m = wid >> 2, warp_n = wid & 3;
    const int jBase = blockIdx.x * 128;
    const int mBase = blockIdx.y * 128;

    float acc[4][4][4];
#pragma unroll
    for (int i = 0; i < 4; i++)
#pragma unroll
        for (int j = 0; j < 4; j++)
#pragma unroll
            for (int k = 0; k < 4; k++) acc[i][j][k] = 0.f;

    gemm_core<FEAT_I, 6 * (FEAT_I / 64)>(
        (const char*)(g_xb + (size_t)mBase * K3_1),
        (const char*)(g_w1b + (size_t)jBase * K3_1), tid, smb, acc);

    // bias + relu in place
    float bv[4][2];
#pragma unroll
    for (int in = 0; in < 4; in++)
#pragma unroll
        for (int e = 0; e < 2; e++)
            bv[in][e] = __ldg(&b1[jBase + warp_n * 32 + in * 8 + (lane & 3) * 2 + e]);
#pragma unroll
    for (int im = 0; im < 4; im++)
#pragma unroll
        for (int in = 0; in < 4; in++)
#pragma unroll
            for (int rr = 0; rr < 2; rr++)
#pragma unroll
                for (int e = 0; e < 2; e++) {
                    float z = acc[im][in][rr * 2 + e] + bv[in][e];
                    acc[im][in][rr * 2 + e] = z > 0.f ? z : 0.f;
                }

    // 3 planes: peel bf16, stage in smem [128][128] bf16, coalesced copy-out
    __nv_bfloat16* stage = (__nv_bfloat16*)smem;
#pragma unroll
    for (int p = 0; p < 3; p++) {
#pragma unroll
        for (int im = 0; im < 4; im++)
#pragma unroll
            for (int in = 0; in < 4; in++)
#pragma unroll
                for (int rr = 0; rr < 2; rr++) {
                    const int r = warp_m * 64 + im * 16 + (lane >> 2) + rr * 8;
                    const int col = warp_n * 32 + in * 8 + (lane & 3) * 2;
                    __nv_bfloat162 v;
#pragma unroll
                    for (int e = 0; e < 2; e++) {
                        float z = acc[im][in][rr * 2 + e];
                        __nv_bfloat16 hp = __float2bfloat16(z);
                        acc[im][in][rr * 2 + e] = z - __bfloat162float(hp);
                        ((__nv_bfloat16*)&v)[e] = hp;
                    }
                    *(__nv_bfloat162*)&stage[r * 128 + col] = v;
                }
        __syncthreads();
#pragma unroll
        for (int i = 0; i < 8; i++) {
            const int id = tid + 256 * i;          // 2048 float4
            const int r = id >> 4, c4 = id & 15;
            float4 v = *(const float4*)&stage[r * 128 + c4 * 8];
            *(float4*)&g_hb[(size_t)(mBase + r) * K3_2 + p * H_DIM + jBase + c4 * 8] = v;
        }
        __syncthreads();
    }
}

// ---------------------------------------------------------------------------
// GEMM2: logits = h@W2 + b2 + gumbel -> g_logits (fp32)
// ---------------------------------------------------------------------------
__global__ __launch_bounds__(256, 2)
void gemm2_mma(const float* __restrict__ b2, const float* __restrict__ gumbel_u) {
    extern __shared__ char smem[];
    const uint32_t smb = smem_u32(smem);
    const int tid = threadIdx.x, lane = tid & 31, wid = tid >> 5;
    const int warp_m = wid >> 2, warp_n = wid & 3;
    const int jBase = blockIdx.x * 128;
    const int mBase = blockIdx.y * 128;

    float acc[4][4][4];
#pragma unroll
    for (int i = 0; i < 4; i++)
#pragma unroll
        for (int j = 0; j < 4; j++)
#pragma unroll
            for (int k = 0; k < 4; k++) acc[i][j][k] = 0.f;

    gemm_core<H_DIM, 6 * (H_DIM / 64)>(
        (const char*)(g_hb + (size_t)mBase * K3_2),
        (const char*)(g_w2b + (size_t)jBase * K3_2), tid, smb, acc);

    float bv[4][2];
#pragma unroll
    for (int in = 0; in < 4; in++)
#pragma unroll
        for (int e = 0; e < 2; e++)
            bv[in][e] = __ldg(&b2[jBase + warp_n * 32 + in * 8 + (lane & 3) * 2 + e]);

#pragma unroll
    for (int im = 0; im < 4; im++)
#pragma unroll
        for (int in = 0; in < 4; in++)
#pragma unroll
            for (int rr = 0; rr < 2; rr++) {
                const int m = mBase + warp_m * 64 + im * 16 + (lane >> 2) + rr * 8;
                const int j = jBase + warp_n * 32 + in * 8 + (lane & 3) * 2;
                const float2 u = *(const float2*)&gumbel_u[(size_t)m * CODE + j];
                float2 o;
                o.x = acc[im][in][rr * 2 + 0] + bv[in][0]
                      - logf(-logf(u.x + 1e-10f) + 1e-10f);
                o.y = acc[im][in][rr * 2 + 1] + bv[in][1]
                      - logf(-logf(u.y + 1e-10f) + 1e-10f);
                *(float2*)&g_logits[(size_t)m * CODE + j] = o;
            }
}

// ---------------------------------------------------------------------------
// Conversion kernels (tiled transpose + 3-plane split)
// ---------------------------------------------------------------------------
__global__ __launch_bounds__(256)
void conv_x_kernel(const float* __restrict__ series) {
    __shared__ float s[32][33];
    const int k0 = blockIdx.x * 32, t0 = blockIdx.y * 32, b = blockIdx.z;
    const int tx = threadIdx.x, ty = threadIdx.y;
#pragma unroll
    for (int i = 0; i < 4; i++) {
        int kk = ty + 8 * i;
        s[kk][tx] = series[((size_t)b * FEAT_I + k0 + kk) * T_ + t0 + tx];
    }
    __syncthreads();
#pragma unroll
    for (int i = 0; i < 4; i++) {
        int tt = ty + 8 * i;
        int m = b * T_ + t0 + tt;
        float v = s[tx][tt];
        __nv_bfloat16 h, md, l;
        split3(v, h, md, l);
        __nv_bfloat16* row = g_xb + (size_t)m * K3_1;
        row[0 * FEAT_I + k0 + tx] = h;
        row[1 * FEAT_I + k0 + tx] = md;
        row[2 * FEAT_I + k0 + tx] = l;
    }
}

__global__ __launch_bounds__(256)
void conv_w1_kernel(const float* __restrict__ W1) {
    __shared__ float s[32][33];
    const int k0 = blockIdx.x * 32, n0 = blockIdx.y * 32;
    const int tx = threadIdx.x, ty = threadIdx.y;
#pragma unroll
    for (int i = 0; i < 4; i++) {
        int kk = ty + 8 * i;
        s[kk][tx] = W1[(size_t)(k0 + kk) * H_DIM + n0 + tx];
    }
    __syncthreads();
#pragma unroll
    for (int i = 0; i < 4; i++) {
        int nn = ty + 8 * i;
        float v = s[tx][nn];
        __nv_bfloat16 h, md, l;
        split3(v, h, md, l);
        __nv_bfloat16* row = g_w1b + (size_t)(n0 + nn) * K3_1;
        row[0 * FEAT_I + k0 + tx] = h;
        row[1 * FEAT_I + k0 + tx] = md;
        row[2 * FEAT_I + k0 + tx] = l;
    }
}

__global__ __launch_bounds__(256)
void conv_w2_kernel(const float* __restrict__ W2) {
    __shared__ float s[32][33];
    const int k0 = blockIdx.x * 32, n0 = blockIdx.y * 32;
    const int tx = threadIdx.x, ty = threadIdx.y;
#pragma unroll
    for (int i = 0; i < 4; i++) {
        int kk = ty + 8 * i;
        s[kk][tx] = W2[(size_t)(k0 + kk) * CODE + n0 + tx];
    }
    __syncthreads();
#pragma unroll
    for (int i = 0; i < 4; i++) {
        int nn = ty + 8 * i;
        float v = s[tx][nn];
        __nv_bfloat16 h, md, l;
        split3(v, h, md, l);
        __nv_bfloat16* row = g_w2b + (size_t)(n0 + nn) * K3_2;
        row[0 * H_DIM + k0 + tx] = h;
        row[1 * H_DIM + k0 + tx] = md;
        row[2 * H_DIM + k0 + tx] = l;
    }
}

// ---------------------------------------------------------------------------
// Argmax over 320 perturbed logits per (n,g) + codebook gather (t-coalesced)
// ---------------------------------------------------------------------------
__global__ __launch_bounds__(256)
void argmax_gather_kernel(const float* __restrict__ codebook,
                          float* __restrict__ out)
{
    const int t0 = blockIdx.x * 32;
    const int b  = blockIdx.y;
    const int g  = blockIdx.z;

    __shared__ int s_idx[32];

    const int tid  = threadIdx.x;
    const int lane = tid & 31;
    const int w    = tid >> 5;

#pragma unroll
    for (int rr = 0; rr < 4; rr++) {
        const int tl = w * 4 + rr;
        const int n  = b * T_ + t0 + tl;
        const float* lp = g_logits + (size_t)n * CODE + g * CODE_G;
        float best = -INFINITY;
        int   bi   = 0;
        for (int c = lane; c < CODE_G; c += 32) {
            float v = lp[c];
            if (v > best) { best = v; bi = c; }
        }
#pragma unroll
        for (int off = 16; off; off >>= 1) {
            float ov = __shfl_down_sync(0xffffffffu, best, off);
            int   oi = __shfl_down_sync(0xffffffffu, bi,   off);
            if (ov > best || (ov == best && oi < bi)) { best = ov; bi = oi; }
        }
        if (lane == 0) {
            s_idx[tl] = bi;
            out[Q_ELEMS + (size_t)n * 2 + g] = (float)bi;
        }
    }
    __syncthreads();

    const int tx  = tid & 31;
    const int fy  = tid >> 5;
    const int idx = s_idx[tx];
    const float* cbrow = codebook + ((size_t)g * CODE_G + idx) * FEAT_G;
    float* outb = out + ((size_t)b * 512 + g * FEAT_G) * T_ + t0;
    for (int f = fy; f < FEAT_G; f += 8)
        outb[(size_t)f * T_ + tx] = cbrow[f];
}

// ---------------------------------------------------------------------------
extern "C" void kernel_launch(void* const* d_in, const int* in_sizes, int n_in,
                              void* d_out, int out_size)
{
    const float* series   = (const float*)d_in[0];
    const float* gumbel_u = (const float*)d_in[1];
    const float* W1       = (const float*)d_in[2];
    const float* b1       = (const float*)d_in[3];
    const float* W2       = (const float*)d_in[4];
    const float* b2       = (const float*)d_in[5];
    const float* codebook = (const float*)d_in[6];
    float* out = (float*)d_out;

    static int attr_done = 0;
    if (!attr_done) {
        cudaFuncSetAttribute(gemm1_mma, cudaFuncAttributeMaxDynamicSharedMemorySize, 65536);
        cudaFuncSetAttribute(gemm2_mma, cudaFuncAttributeMaxDynamicSharedMemorySize, 65536);
        attr_done = 1;
    }

    conv_x_kernel <<<dim3(FEAT_I / 32, T_ / 32, B_), dim3(32, 8)>>>(series);
    conv_w1_kernel<<<dim3(FEAT_I / 32, H_DIM / 32),  dim3(32, 8)>>>(W1);
    conv_w2_kernel<<<dim3(H_DIM / 32, CODE / 32),    dim3(32, 8)>>>(W2);

    gemm1_mma<<<dim3(H_DIM / 128, N_ / 128), 256, 65536>>>(b1);
    gemm2_mma<<<dim3(CODE / 128,  N_ / 128), 256, 65536>>>(b2, gumbel_u);

    argmax_gather_kernel<<<dim3(T_ / 32, B_, 2), 256>>>(codebook, out);
}